// round 10
// baseline (speedup 1.0000x reference)
#include <cuda_runtime.h>

#define NTOT   32768      // 64 graphs * 512 nodes
#define NB     64
#define NPG    512
#define LIG    128
#define GN_PER_G 1020
#define GG_PER_G 2
#define GFIXPG (GN_PER_G + GG_PER_G)          // 1022
#define GFIX   (NB * GFIXPG)                  // 65408
#define FULL   0xffffffffu

// d = __fsqrt_rn(d2);  d <= 8  <=>  d2 <= 64+1ulp ;  d <= 10 <=> d2 <= 100+1ulp
#define T8_BITS  0x42800001
#define T10_BITS 0x42C80001

// Scratch (device globals; zero-initialized at load; d_arrive self-resets)
__device__ unsigned d_mask_ctx[NTOT * 16];
__device__ unsigned d_mask_inter[NTOT * 16];
__device__ int d_cnt_ctx[NTOT];
__device__ int d_cnt_inter[NTOT];
__device__ int d_off_ctx[NTOT];     // within-graph exclusive row offsets
__device__ int d_off_inter[NTOT];
__device__ int d_graph_ctx[NB];
__device__ int d_graph_inter[NB];
__device__ int d_red_cnt[NB];
__device__ int d_arrive[NB];

__device__ __forceinline__ int warp_incl_scan(int x) {
    #pragma unroll
    for (int d = 1; d < 32; d <<= 1) {
        int y = __shfl_up_sync(FULL, x, d);
        if ((threadIdx.x & 31) >= d) x += y;
    }
    return x;
}

// One warp scans a 64-int array: exclusive prefix -> sh_excl[64], total -> *sh_tot.
__device__ __forceinline__ void warp_scan64_sh(const int* __restrict__ in,
                                               int* sh_excl, int* sh_tot) {
    int lane = threadIdx.x & 31;
    int v0 = in[2 * lane], v1 = in[2 * lane + 1];
    int s = v0 + v1;
    int x = warp_incl_scan(s);
    int excl = x - s;
    sh_excl[2 * lane]     = excl;
    sh_excl[2 * lane + 1] = excl + v0;
    if (lane == 31) *sh_tot = x;
}

__device__ __forceinline__ int block_excl_scan512(int v, int* sw) {
    int lane = threadIdx.x & 31, wid = threadIdx.x >> 5;
    int x = warp_incl_scan(v);
    if (lane == 31) sw[wid] = x;
    __syncthreads();
    if (wid == 0) {
        int t = (lane < 16) ? sw[lane] : 0;
        t = warp_incl_scan(t);
        if (lane < 16) sw[lane] = t;
    }
    __syncthreads();
    int add = wid ? sw[wid - 1] : 0;
    return x - v + add;
}

// ---- count: 4 rows per warp, 64 rows per block, fused per-graph scan (R7) ----
__global__ void __launch_bounds__(512) count_kernel(const float* __restrict__ X) {
    __shared__ float4 s_pos[NPG];
    __shared__ int sw[16];
    __shared__ int s_last, s_red;
    int tid  = threadIdx.x, lane = tid & 31, wid = tid >> 5;
    int blk  = blockIdx.x;                     // 512 blocks, 8 per graph
    int b    = blk >> 3;
    int base = b << 9;
    int li0  = (blk & 7) * 64 + wid * 4;       // first of this warp's 4 rows

    {
        const float* gp = X + 3 * base;
        int t = tid;
        s_pos[t] = make_float4(gp[3 * t], gp[3 * t + 1], gp[3 * t + 2], 0.f);
    }
    __syncthreads();

    const float t8  = __int_as_float(T8_BITS);
    const float t10 = __int_as_float(T10_BITS);

    float4 a0 = s_pos[li0 + 0];
    float4 a1 = s_pos[li0 + 1];
    float4 a2 = s_pos[li0 + 2];
    float4 a3 = s_pos[li0 + 3];
    float hi0 = (li0 + 0 > LIG) ? t8 : t10;
    float hi1 = (li0 + 1 > LIG) ? t8 : t10;
    float hi2 = (li0 + 2 > LIG) ? t8 : t10;
    float hi3 = (li0 + 3 > LIG) ? t8 : t10;

    unsigned mb0 = 0u, mb1 = 0u, mb2 = 0u, mb3 = 0u;   // lane k keeps word k

    #pragma unroll
    for (int k = 0; k < 16; k++) {
        float4 p = s_pos[k * 32 + lane];
        #define PAIR(A, HI, MB)                                                   \
        {                                                                         \
            float dx = __fadd_rn(A.x, -p.x);                                      \
            float dy = __fadd_rn(A.y, -p.y);                                      \
            float dz = __fadd_rn(A.z, -p.z);                                      \
            float d2 = __fadd_rn(__fadd_rn(__fmul_rn(dx, dx), __fmul_rn(dy, dy)), \
                                 __fmul_rn(dz, dz));                              \
            float thr = (k < 4) ? t10 : HI;                                       \
            unsigned m = __ballot_sync(FULL, d2 <= thr);                          \
            if (lane == k) MB = m;                                                \
        }
        PAIR(a0, hi0, mb0)
        PAIR(a1, hi1, mb1)
        PAIR(a2, hi2, mb2)
        PAIR(a3, hi3, mb3)
        #undef PAIR
    }

    unsigned LIGWl  = (lane == 0) ? 0xFFFFFFFEu : ((lane < 4)  ? FULL : 0u);
    unsigned PROTWl = (lane < 4)  ? 0u          : ((lane == 4) ? 0xFFFFFFFEu : FULL);

    #define EMIT(R, MB)                                                          \
    {                                                                            \
        int li = li0 + R, i = base + li;                                         \
        unsigned pm = (li > LIG) ? FULL : 0u;                                    \
        unsigned lm = (li >= 1 && li < LIG) ? FULL : 0u;                         \
        unsigned myc  = MB & PROTWl & pm;                                        \
        unsigned mymi = (MB & LIGWl & pm) | (MB & PROTWl & lm);                  \
        if (pm && lane == (li >> 5)) myc &= ~(1u << (li & 31));                  \
        if (lane < 16) {                                                         \
            d_mask_ctx[(i << 4) + lane]   = myc;                                 \
            d_mask_inter[(i << 4) + lane] = mymi;                                \
        }                                                                        \
        int val = (lane < 16) ? (__popc(myc) | (__popc(mymi) << 16)) : 0;        \
        _Pragma("unroll")                                                        \
        for (int d = 16; d; d >>= 1) val += __shfl_down_sync(FULL, val, d);      \
        if (lane == 0) {                                                         \
            d_cnt_ctx[i]   = val & 0xffff;                                       \
            d_cnt_inter[i] = val >> 16;                                          \
        }                                                                        \
    }
    EMIT(0, mb0)
    EMIT(1, mb1)
    EMIT(2, mb2)
    EMIT(3, mb3)
    #undef EMIT

    __syncthreads();
    if (tid == 0) {
        __threadfence();
        s_last = atomicAdd(&d_arrive[b], 1);
        s_red  = 0;
    }
    __syncthreads();
    if (s_last == 7) {
        __threadfence();
        int t = tid, row = base + t;

        int vc = d_cnt_ctx[row];
        int ec = block_excl_scan512(vc, sw);
        d_off_ctx[row] = ec;
        if (t == 511) d_graph_ctx[b] = ec + vc;
        __syncthreads();

        int vi = d_cnt_inter[row];
        int ei = block_excl_scan512(vi, sw);
        d_off_inter[row] = ei;
        if (t == 511) d_graph_inter[b] = ei + vi;

        int vr = (t >= 1 && t < LIG) ? vi : 0;
        #pragma unroll
        for (int d = 16; d; d >>= 1) vr += __shfl_down_sync(FULL, vr, d);
        if (lane == 0 && vr) atomicAdd(&s_red, vr);
        __syncthreads();
        if (t == 0) {
            d_red_cnt[b] = s_red;
            d_arrive[b]  = 0;
        }
    }
}

// ---- write: warp per row, rank-based coalesced emission via shfl + __fns ----
// lanes 0-11: "A" words (prot: ctx w4..15 ; lig: inter w4..15)
// lanes 12-15: "B" words (prot: inter w0..3)
__global__ void __launch_bounds__(512) write_kernel(float* __restrict__ out) {
    __shared__ int sgc[NB], sgi[NB], sro[NB];
    __shared__ int stc_, sti_, str_;
    int tid = threadIdx.x, lane = tid & 31, wid = tid >> 5;
    int blk  = blockIdx.x;                      // 2048 blocks, 32 per graph
    int b    = blk >> 5;
    int s    = blk & 31;                        // slice 0..31 of graph
    int base = b << 9;
    int li   = s * 16 + wid;                    // this warp's row (local)
    int i    = base + li;

    if (wid == 0)      warp_scan64_sh(d_graph_ctx,   sgc, &stc_);
    else if (wid == 1) warp_scan64_sh(d_graph_inter, sgi, &sti_);
    else if (wid == 2) warp_scan64_sh(d_red_cnt,     sro, &str_);
    __syncthreads();

    int EcR = stc_;
    int Ec  = EcR + GFIX;
    int Ei  = sti_;
    int Er  = str_;

    bool prot = li > LIG;
    bool lig  = (li >= 1) && (li < LIG);

    unsigned word = 0u;
    if (lane < 12) {
        if (prot)      word = d_mask_ctx[(i << 4) + 4 + lane];
        else if (lig)  word = d_mask_inter[(i << 4) + 4 + lane];
    } else if (lane < 16 && prot) {
        word = d_mask_inter[(i << 4) + (lane - 12)];
    }

    int cnt  = __popc(word);
    int I    = warp_incl_scan(cnt);
    int excl = I - cnt;
    int TA   = __shfl_sync(FULL, I, 11);
    int I15  = __shfl_sync(FULL, I, 15);
    int TB   = I15 - TA;

    int posA, colAddA;
    if (prot) { posA = sgc[b] + d_off_ctx[i];            colAddA = Ec; }
    else      { posA = 2 * Ec + sgi[b] + d_off_inter[i]; colAddA = Ei; }
    int posB = 2 * Ec + sgi[b] + d_off_inter[i];         // prot inter (lig cols)

    float fi = (float)i;

    for (int e0 = 0; e0 < TA; e0 += 32) {       // category A, coalesced
        int e = e0 + lane;
        int lo = 0;
        #pragma unroll
        for (int st = 8; st; st >>= 1) {
            int t = lo + st;
            int tv = __shfl_sync(FULL, excl, (t < 12) ? t : 11);  // all lanes shfl
            if (t < 12 && tv <= e) lo = t;
        }
        unsigned wv = __shfl_sync(FULL, word, lo);
        int rank = e - __shfl_sync(FULL, excl, lo);
        int bit  = __fns(wv, 0, rank + 1);
        if (e < TA) {
            out[posA + e]           = fi;
            out[posA + e + colAddA] = (float)(base + (4 + lo) * 32 + bit);
        }
    }

    for (int e0 = 0; e0 < TB; e0 += 32) {       // category B (prot inter), coalesced
        int e = e0 + lane;
        int lo = 12;
        #pragma unroll
        for (int st = 2; st; st >>= 1) {
            int t = lo + st;
            int tv = __shfl_sync(FULL, excl, (t < 16) ? t : 15);  // all lanes shfl
            if (t < 16 && (tv - TA) <= e) lo = t;
        }
        unsigned wv = __shfl_sync(FULL, word, lo);
        int rank = e - (__shfl_sync(FULL, excl, lo) - TA);
        int bit  = __fns(wv, 0, rank + 1);
        if (e < TB) {
            out[posB + e]      = fi;
            out[posB + e + Ei] = (float)(base + (lo - 12) * 32 + bit);
        }
    }

    // fixed global edges: slice s handles idx in [32s, 32s+32)
    if (tid < 32) {
        int idx = s * 32 + tid;
        if (idx < GFIXPG) {
            int r, c, p;
            if (idx < GN_PER_G) {
                p = EcR + b * GN_PER_G + idx;
                if (idx < 127)        { r = 0;               c = 1 + idx; }
                else if (idx < 254)   { r = idx - 126;       c = 0; }
                else if (idx < 637)   { r = 128;             c = idx - 254 + 129; }
                else                  { r = idx - 637 + 129; c = 128; }
            } else {
                int k = idx - GN_PER_G;
                p = EcR + NB * GN_PER_G + b * 2 + k;
                r = k ? 128 : 0;
                c = k ? 0   : 128;
            }
            out[p]      = (float)(base + r);
            out[Ec + p] = (float)(base + c);
        }
    }

    // reduced arrays: contiguous chunk per slice (coalesced)
    int rcnt = d_red_cnt[b];
    int roff = sro[b];
    int chunk = (rcnt + 31) >> 5;
    int k0 = s * chunk;
    int k1 = min(k0 + chunk, rcnt);
    int base1 = 2 * Ec + 2 * Ei + roff;
    int base2 = base1 + Er;
    float fb = (float)b, fo = (float)base;
    for (int k = k0 + tid; k < k1; k += 512) {
        out[base1 + k] = fb;
        out[base2 + k] = fo;
    }
}

extern "C" void kernel_launch(void* const* d_in, const int* in_sizes, int n_in,
                              void* d_out, int out_size) {
    const float* X = (const float*)d_in[0];
    for (int k = 0; k < n_in; k++) {
        if (in_sizes[k] == 3 * NTOT) { X = (const float*)d_in[k]; break; }
    }
    float* out = (float*)d_out;
    (void)out_size;

    count_kernel<<<NTOT / 64, 512>>>(X);
    write_kernel<<<NTOT / 16, 512>>>(out);
}

// round 11
// speedup vs baseline: 1.4024x; 1.4024x over previous
#include <cuda_runtime.h>

#define NTOT   32768      // 64 graphs * 512 nodes
#define NB     64
#define NPG    512
#define LIG    128
#define GN_PER_G 1020
#define GG_PER_G 2
#define GFIXPG (GN_PER_G + GG_PER_G)          // 1022
#define GFIX   (NB * GFIXPG)                  // 65408
#define FULL   0xffffffffu

// d = __fsqrt_rn(d2);  d <= 8  <=>  d2 <= 64+1ulp ;  d <= 10 <=> d2 <= 100+1ulp
#define T8_BITS  0x42800001
#define T10_BITS 0x42C80001

// Scratch (device globals; zero-initialized at load; d_arrive self-resets)
__device__ unsigned d_mask_ctx[NTOT * 16];
__device__ unsigned d_mask_inter[NTOT * 16];
__device__ int d_off_ctx[NTOT];     // within-graph exclusive row offsets
__device__ int d_off_inter[NTOT];
__device__ int d_graph_ctx[NB];
__device__ int d_graph_inter[NB];
__device__ int d_red_cnt[NB];
__device__ int d_arrive[NB];

__device__ __forceinline__ int warp_incl_scan(int x) {
    #pragma unroll
    for (int d = 1; d < 32; d <<= 1) {
        int y = __shfl_up_sync(FULL, x, d);
        if ((threadIdx.x & 31) >= d) x += y;
    }
    return x;
}

// One warp scans a 64-int array: exclusive prefix -> sh_excl[64], total -> *sh_tot.
__device__ __forceinline__ void warp_scan64_sh(const int* __restrict__ in,
                                               int* sh_excl, int* sh_tot) {
    int lane = threadIdx.x & 31;
    int v0 = in[2 * lane], v1 = in[2 * lane + 1];
    int s = v0 + v1;
    int x = warp_incl_scan(s);
    int excl = x - s;
    sh_excl[2 * lane]     = excl;
    sh_excl[2 * lane + 1] = excl + v0;
    if (lane == 31) *sh_tot = x;
}

__device__ __forceinline__ int block_excl_scan512(int v, int* sw) {
    int lane = threadIdx.x & 31, wid = threadIdx.x >> 5;
    int x = warp_incl_scan(v);
    if (lane == 31) sw[wid] = x;
    __syncthreads();
    if (wid == 0) {
        int t = (lane < 16) ? sw[lane] : 0;
        t = warp_incl_scan(t);
        if (lane < 16) sw[lane] = t;
    }
    __syncthreads();
    int add = wid ? sw[wid - 1] : 0;
    return x - v + add;
}

// 32x32 bit-matrix transpose across a warp (lane = row of bit matrix).
__device__ __forceinline__ unsigned transpose32(unsigned x, int lane) {
    #pragma unroll
    for (int s = 16; s; s >>= 1) {
        unsigned m = (s == 16) ? 0x0000FFFFu : (s == 8) ? 0x00FF00FFu :
                     (s == 4)  ? 0x0F0F0F0Fu : (s == 2) ? 0x33333333u : 0x55555555u;
        unsigned q = __shfl_xor_sync(FULL, x, s);
        x = (lane & s) ? ((x & ~m) | ((q & ~m) >> s))
                       : ((x & m)  | ((q & m)  << s));
    }
    return x;
}

// Store word for (rowTile R, colWord C) with all boundary fixes applied.
__device__ __forceinline__ void store_word(unsigned w, int gbase, int R, int C, int lane) {
    if (C == 0 || C == 4) w &= ~1u;              // global columns 0 / 128
    if ((R == 0 || R == 4) && lane == 0) w = 0u; // global rows 0 / 128
    if (R == C) w &= ~(1u << lane);              // self pairs on diagonal
    int idx = ((gbase + R * 32 + lane) << 4) + C;
    if (R < 4 || C < 4) d_mask_inter[idx] = w;   // lig-lig tiles never reach here
    else                d_mask_ctx[idx]   = w;
}

// ---- count: symmetric tile-pair enumeration, ballot-free, fused scan ----
__global__ void __launch_bounds__(512) count_kernel(const float* __restrict__ X) {
    __shared__ float4 s_pos[NPG];
    __shared__ int sw[16];
    __shared__ int s_last, s_red;
    int tid  = threadIdx.x, lane = tid & 31, wid = tid >> 5;
    int blk  = blockIdx.x;                     // 256 blocks, 4 per graph
    int b    = blk >> 2;
    int gbase = b << 9;
    int W    = (blk & 3) * 16 + wid;           // warp id within graph, 0..63

    {
        const float* gp = X + 3 * gbase;
        int t = tid;
        s_pos[t] = make_float4(gp[3 * t], gp[3 * t + 1], gp[3 * t + 2], 0.f);
    }
    __syncthreads();

    const float t8  = __int_as_float(T8_BITS);
    const float t10 = __int_as_float(T10_BITS);

    // 136 unordered tile-pair tasks per graph
    for (int tt = W; tt < 136; tt += 64) {
        int I, J;
        if (tt < 16)       { I = tt; J = tt; }
        else if (tt < 128) { int u = tt - 16; int bd = (u >> 4) + 1;
                             I = u & 15; J = (I + bd) & 15; }
        else               { I = tt - 128; J = I + 8; }
        if (I < 4 && J < 4) continue;          // lig-lig: no edge category
        float thr = (I >= 4 && J >= 4) ? t8 : t10;

        float4 p = s_pos[J * 32 + lane];       // lane owns column J*32+lane
        unsigned x = 0u;
        #pragma unroll
        for (int r = 0; r < 32; r++) {
            float4 a = s_pos[I * 32 + r];      // uniform broadcast load
            float dx = __fadd_rn(a.x, -p.x);
            float dy = __fadd_rn(a.y, -p.y);
            float dz = __fadd_rn(a.z, -p.z);
            float d2 = __fadd_rn(__fadd_rn(__fmul_rn(dx, dx), __fmul_rn(dy, dy)),
                                 __fmul_rn(dz, dz));
            if (d2 <= thr) x |= (1u << r);
        }
        // x (lane j): bit r = edge(I*32+r, J*32+j) = row (J*32+j), word I, bit r
        store_word(x, gbase, J, I, lane);
        if (I != J) {
            unsigned y = transpose32(x, lane); // row (I*32+lane), word J
            store_word(y, gbase, I, J, lane);
        }
    }

    // ---- last arriving block of this graph: counts from masks + scans ----
    __syncthreads();
    if (tid == 0) {
        __threadfence();
        s_last = atomicAdd(&d_arrive[b], 1);
        s_red  = 0;
    }
    __syncthreads();
    if (s_last == 3) {
        __threadfence();
        int t = tid, i = gbase + t;

        int vc = 0, vi = 0;
        const uint4* mc = (const uint4*)&d_mask_ctx[i << 4];
        const uint4* mi = (const uint4*)&d_mask_inter[i << 4];
        if (t > LIG) {                          // protein row
            uint4 c1 = mc[1], c2 = mc[2], c3 = mc[3];
            vc = __popc(c1.x) + __popc(c1.y) + __popc(c1.z) + __popc(c1.w)
               + __popc(c2.x) + __popc(c2.y) + __popc(c2.z) + __popc(c2.w)
               + __popc(c3.x) + __popc(c3.y) + __popc(c3.z) + __popc(c3.w);
            uint4 i0 = mi[0];
            vi = __popc(i0.x) + __popc(i0.y) + __popc(i0.z) + __popc(i0.w);
        } else if (t >= 1 && t < LIG) {         // ligand row
            uint4 i1 = mi[1], i2 = mi[2], i3 = mi[3];
            vi = __popc(i1.x) + __popc(i1.y) + __popc(i1.z) + __popc(i1.w)
               + __popc(i2.x) + __popc(i2.y) + __popc(i2.z) + __popc(i2.w)
               + __popc(i3.x) + __popc(i3.y) + __popc(i3.z) + __popc(i3.w);
        }

        int ec = block_excl_scan512(vc, sw);
        d_off_ctx[i] = ec;
        if (t == 511) d_graph_ctx[b] = ec + vc;
        __syncthreads();

        int ei = block_excl_scan512(vi, sw);
        d_off_inter[i] = ei;
        if (t == 511) d_graph_inter[b] = ei + vi;

        int vr = (t >= 1 && t < LIG) ? vi : 0;  // reduced = ligand-row inter edges
        #pragma unroll
        for (int d = 16; d; d >>= 1) vr += __shfl_down_sync(FULL, vr, d);
        if (lane == 0 && vr) atomicAdd(&s_red, vr);
        __syncthreads();
        if (t == 0) {
            d_red_cnt[b] = s_red;
            d_arrive[b]  = 0;                   // reset for next graph replay
        }
    }
}

// ---- write: 2 rows per warp, active-word compression (proven R7 version) ----
__global__ void __launch_bounds__(512) write_kernel(float* __restrict__ out) {
    __shared__ int sgc[NB], sgi[NB], sro[NB];
    __shared__ int stc_, sti_, str_;
    int tid = threadIdx.x, lane = tid & 31, wid = tid >> 5;
    int blk  = blockIdx.x;                      // 1024 blocks
    int b    = blk >> 4;
    int s    = blk & 15;                        // slice 0..15 of graph
    int base = b << 9;

    if (wid == 0)      warp_scan64_sh(d_graph_ctx,   sgc, &stc_);
    else if (wid == 1) warp_scan64_sh(d_graph_inter, sgi, &sti_);
    else if (wid == 2) warp_scan64_sh(d_red_cnt,     sro, &str_);
    __syncthreads();

    int EcR = stc_;
    int Ec  = EcR + GFIX;
    int Ei  = sti_;
    int Er  = str_;

    int half = lane >> 4;
    int slot = lane & 15;
    int li   = s * 32 + wid * 2 + half;         // local row within graph
    int i    = base + li;

    bool prot = li > LIG;
    bool lig  = (li >= 1) && (li < LIG);
    int wIdx  = (slot < 12) ? (4 + slot) : (slot - 12);

    unsigned word = 0u;
    bool isCtx = false;
    if (prot) {
        word  = (slot < 12) ? d_mask_ctx[(i << 4) + wIdx]
                            : d_mask_inter[(i << 4) + wIdx];
        isCtx = slot < 12;
    } else if (lig && slot < 12) {
        word = d_mask_inter[(i << 4) + wIdx];
    }

    int cnt = __popc(word);
    int I   = warp_incl_scan(cnt);
    int I11 = __shfl_sync(FULL, I, 11);
    int I15 = __shfl_sync(FULL, I, 15);
    int I27 = __shfl_sync(FULL, I, 27);
    int sub0 = half ? I15 : 0;
    int sub1 = half ? I27 : I11;
    int excl = I - cnt - ((slot < 12) ? sub0 : sub1);

    int pos, colAdd;
    if (isCtx) { pos = sgc[b] + d_off_ctx[i] + excl;            colAdd = Ec; }
    else       { pos = 2 * Ec + sgi[b] + d_off_inter[i] + excl; colAdd = Ei; }

    float fi = (float)i;
    int cbase = base + wIdx * 32;
    while (word) {
        int bit = __ffs(word) - 1;
        word &= word - 1;
        out[pos]          = fi;
        out[pos + colAdd] = (float)(cbase + bit);
        pos++;
    }

    // fixed global edges: slice s handles idx in [64s, 64s+64)
    if (tid < 64) {
        int idx = s * 64 + tid;
        if (idx < GFIXPG) {
            int r, c, p;
            if (idx < GN_PER_G) {
                p = EcR + b * GN_PER_G + idx;
                if (idx < 127)        { r = 0;               c = 1 + idx; }
                else if (idx < 254)   { r = idx - 126;       c = 0; }
                else if (idx < 637)   { r = 128;             c = idx - 254 + 129; }
                else                  { r = idx - 637 + 129; c = 128; }
            } else {
                int k = idx - GN_PER_G;
                p = EcR + NB * GN_PER_G + b * 2 + k;
                r = k ? 128 : 0;
                c = k ? 0   : 128;
            }
            out[p]      = (float)(base + r);
            out[Ec + p] = (float)(base + c);
        }
    }

    // reduced arrays: contiguous chunk per slice (coalesced)
    int rcnt = d_red_cnt[b];
    int roff = sro[b];
    int chunk = (rcnt + 15) >> 4;
    int k0 = s * chunk;
    int k1 = min(k0 + chunk, rcnt);
    int base1 = 2 * Ec + 2 * Ei + roff;
    int base2 = base1 + Er;
    float fb = (float)b, fo = (float)base;
    for (int k = k0 + tid; k < k1; k += 512) {
        out[base1 + k] = fb;
        out[base2 + k] = fo;
    }
}

extern "C" void kernel_launch(void* const* d_in, const int* in_sizes, int n_in,
                              void* d_out, int out_size) {
    const float* X = (const float*)d_in[0];
    for (int k = 0; k < n_in; k++) {
        if (in_sizes[k] == 3 * NTOT) { X = (const float*)d_in[k]; break; }
    }
    float* out = (float*)d_out;
    (void)out_size;

    count_kernel<<<NB * 4, 512>>>(X);
    write_kernel<<<NTOT / 32, 512>>>(out);
}